// round 16
// baseline (speedup 1.0000x reference)
#include <cuda_runtime.h>
#include <cuda_fp16.h>
#include <math.h>
#include <stdint.h>

#define H_DIM 4096
#define E_DIM 64
#define TOPK  8
#define BM    128                 // tokens per CTA
#define KC    64                  // K per chunk (= one accumulation segment)
#define NCHUNK (H_DIM / KC)       // 64
#define THREADS 256               // 8 warps: 4 row-groups x 2 expert-halves

#define A_PL  (BM * KC * 2)       // 16384 B per A fp16 plane
#define B_PL  (E_DIM * KC * 2)    // 8192  B per B fp16 plane
#define STAGE_SZ (2 * A_PL + 2 * B_PL)   // 49152 B
#define TILE_SZ (2 * STAGE_SZ)           // 98304 B
#define DYN_SZ (TILE_SZ + 256)

#define W_SCALE   64.0f           // W pre-scale (2^6, exact)
#define OUT_SCALE 0.015625f       // 2^-6
#define LO_SCALE  2048.0f         // lo-plane pre-scale (2^11, exact)
#define LO_FOLD   4.8828125e-4f   // 2^-11

__device__ __forceinline__ uint32_t s2u(const void* p) {
    uint32_t a;
    asm("{ .reg .u64 t; cvta.to.shared.u64 t, %1; cvt.u32.u64 %0, t; }" : "=r"(a) : "l"(p));
    return a;
}
__device__ __forceinline__ uint32_t swz(uint32_t b) { return b ^ ((b >> 3) & 0x70); }

// fp16 2-way split of one float4 (verified R11): v*scale = h + l*2^-11.
__device__ __forceinline__ void cvt_store2(float4 v, float scale,
                                           uint32_t hB, uint32_t lB, int row, int c4) {
    v.x *= scale; v.y *= scale; v.z *= scale; v.w *= scale;
    uint32_t h01, h23;
    asm("cvt.rn.f16x2.f32 %0, %1, %2;" : "=r"(h01) : "f"(v.y), "f"(v.x));
    asm("cvt.rn.f16x2.f32 %0, %1, %2;" : "=r"(h23) : "f"(v.w), "f"(v.z));
    float h0, h1, h2, h3;
    asm("{.reg .b16 lo,hi; mov.b32 {lo,hi}, %2; cvt.f32.f16 %0, lo; cvt.f32.f16 %1, hi;}"
        : "=f"(h0), "=f"(h1) : "r"(h01));
    asm("{.reg .b16 lo,hi; mov.b32 {lo,hi}, %2; cvt.f32.f16 %0, lo; cvt.f32.f16 %1, hi;}"
        : "=f"(h2), "=f"(h3) : "r"(h23));
    float r0 = (v.x - h0) * LO_SCALE, r1 = (v.y - h1) * LO_SCALE;
    float r2 = (v.z - h2) * LO_SCALE, r3 = (v.w - h3) * LO_SCALE;
    uint32_t l01, l23;
    asm("cvt.rn.f16x2.f32 %0, %1, %2;" : "=r"(l01) : "f"(r1), "f"(r0));
    asm("cvt.rn.f16x2.f32 %0, %1, %2;" : "=r"(l23) : "f"(r3), "f"(r2));
    uint32_t off = swz((uint32_t)(row * 128 + c4 * 8));
    asm volatile("st.shared.v2.b32 [%0], {%1,%2};" :: "r"(hB + off), "r"(h01), "r"(h23));
    asm volatile("st.shared.v2.b32 [%0], {%1,%2};" :: "r"(lB + off), "r"(l01), "r"(l23));
}

__device__ __forceinline__ void load_chunk(const float* __restrict__ A,
                                           const float* __restrict__ W,
                                           int m0, int chunk, int tid,
                                           float4* ra, float4* rb) {
    const int k0 = chunk * KC;
    #pragma unroll
    for (int i = 0; i < 8; i++) {                  // 8*256 = 2048 = 128 rows x 16
        int idx = tid + i * THREADS;
        int row = idx >> 4;
        int c4  = idx & 15;
        ra[i] = *reinterpret_cast<const float4*>(A + (size_t)(m0 + row) * H_DIM + k0 + c4 * 4);
    }
    #pragma unroll
    for (int i = 0; i < 4; i++) {                  // 4*256 = 1024 = 64 rows x 16
        int idx = tid + i * THREADS;
        int row = idx >> 4;
        int c4  = idx & 15;
        rb[i] = *reinterpret_cast<const float4*>(W + (size_t)row * H_DIM + k0 + c4 * 4);
    }
}

__device__ __forceinline__ void ldsm4(uint32_t addr, uint32_t& r0, uint32_t& r1,
                                      uint32_t& r2, uint32_t& r3) {
    asm volatile("ldmatrix.sync.aligned.m8n8.x4.shared.b16 {%0,%1,%2,%3}, [%4];"
                 : "=r"(r0), "=r"(r1), "=r"(r2), "=r"(r3) : "r"(addr));
}

__device__ __forceinline__ void mma16816(float* d, const uint32_t* a, const uint32_t* b) {
    asm volatile(
        "mma.sync.aligned.m16n8k16.row.col.f32.f16.f16.f32 "
        "{%0,%1,%2,%3}, {%4,%5,%6,%7}, {%8,%9}, {%0,%1,%2,%3};"
        : "+f"(d[0]), "+f"(d[1]), "+f"(d[2]), "+f"(d[3])
        : "r"(a[0]), "r"(a[1]), "r"(a[2]), "r"(a[3]), "r"(b[0]), "r"(b[1]));
}

// ---------------------------------------------------------------------------
// HMMA fp16 2-way-split GEMM (numerics == R15), 32x32 warp tiles,
// rotated pipeline: convert(c+1) issues during compute(c)'s mma drain.
// ---------------------------------------------------------------------------
__global__ __launch_bounds__(THREADS, 1) void router_gemm_tc(
    const float* __restrict__ A, const float* __restrict__ W,
    float* __restrict__ logits)
{
    extern __shared__ char dsm[];
    const uint32_t base = (s2u(dsm) + 127u) & ~127u;
    const uint32_t stage_base[2] = { base, base + STAGE_SZ };

    const int tid  = threadIdx.x;
    const int warp = tid >> 5;
    const int lane = tid & 31;
    const int m0   = blockIdx.x * BM;

    const int rg = warp >> 1;     // row group 0..3: rows rg*32 .. rg*32+31
    const int eh = warp & 1;      // expert half: experts eh*32 .. eh*32+31

    const uint32_t a_off0 = (uint32_t)((rg * 32 + (lane & 15)) * 128 + (lane >> 4) * 16);
    const uint32_t b_off0 = (uint32_t)((((lane >> 4) << 3) + (lane & 7)) * 128 +
                                       ((lane >> 3) & 1) * 16 + eh * 2 * 2048);

    float accM[2][4][4];
    #pragma unroll
    for (int mt = 0; mt < 2; mt++)
        #pragma unroll
        for (int nt = 0; nt < 4; nt++)
            #pragma unroll
            for (int j = 0; j < 4; j++) accM[mt][nt][j] = 0.f;

    // ---- prologue: stage chunk 0, prefetch chunk 1 ----
    float4 na[8], nb[4];
    load_chunk(A, W, m0, 0, tid, na, nb);
    {
        const uint32_t aH = stage_base[0], aL = aH + A_PL;
        const uint32_t bH = aL + A_PL,    bL = bH + B_PL;
        #pragma unroll
        for (int i = 0; i < 8; i++) {
            int idx = tid + i * THREADS;
            cvt_store2(na[i], 1.0f, aH, aL, idx >> 4, idx & 15);
        }
        #pragma unroll
        for (int i = 0; i < 4; i++) {
            int idx = tid + i * THREADS;
            cvt_store2(nb[i], W_SCALE, bH, bL, idx >> 4, idx & 15);
        }
    }
    load_chunk(A, W, m0, 1, tid, na, nb);
    __syncthreads();

    for (int chunk = 0; chunk < NCHUNK; ++chunk) {
        const int s  = chunk & 1;
        const int sn = s ^ 1;
        const uint32_t aH = stage_base[s];
        const uint32_t aL = aH + A_PL;
        const uint32_t bH = aL + A_PL;
        const uint32_t bL = bH + B_PL;

        // ---- 1. compute(c) from stage s ----
        float accS0[2][4][4], accS1[2][4][4];
        #pragma unroll
        for (int mt = 0; mt < 2; mt++)
            #pragma unroll
            for (int nt = 0; nt < 4; nt++)
                #pragma unroll
                for (int j = 0; j < 4; j++) { accS0[mt][nt][j] = 0.f; accS1[mt][nt][j] = 0.f; }

        #pragma unroll
        for (int ks = 0; ks < 4; ks++) {
            const uint32_t ka = (uint32_t)(ks * 32);
            uint32_t ah[2][4], al[2][4];
            #pragma unroll
            for (int mt = 0; mt < 2; mt++) {
                const uint32_t ao = a_off0 + (uint32_t)(mt * 16 * 128) + ka;
                ldsm4(aH + swz(ao), ah[mt][0], ah[mt][1], ah[mt][2], ah[mt][3]);
                ldsm4(aL + swz(ao), al[mt][0], al[mt][1], al[mt][2], al[mt][3]);
            }

            uint32_t bh[4][2], bl[4][2];
            const uint32_t bo0 = swz(b_off0 + ka);
            const uint32_t bo1 = swz(b_off0 + 2048 + ka);
            ldsm4(bH + bo0, bh[0][0], bh[0][1], bh[1][0], bh[1][1]);
            ldsm4(bH + bo1, bh[2][0], bh[2][1], bh[3][0], bh[3][1]);
            ldsm4(bL + bo0, bl[0][0], bl[0][1], bl[1][0], bl[1][1]);
            ldsm4(bL + bo1, bl[2][0], bl[2][1], bl[3][0], bl[3][1]);

            #pragma unroll
            for (int mt = 0; mt < 2; mt++) {
                #pragma unroll
                for (int nt = 0; nt < 4; nt++) mma16816(accS0[mt][nt], ah[mt], bh[nt]);
                #pragma unroll
                for (int nt = 0; nt < 4; nt++) mma16816(accS1[mt][nt], al[mt], bh[nt]);
                #pragma unroll
                for (int nt = 0; nt < 4; nt++) mma16816(accS1[mt][nt], ah[mt], bl[nt]);
            }
        }

        // ---- 2. convert(c+1) into stage sn (issues during mma drain) ----
        if (chunk + 1 < NCHUNK) {
            const uint32_t nH = stage_base[sn], nL = nH + A_PL;
            const uint32_t mH = nL + A_PL,      mL = mH + B_PL;
            #pragma unroll
            for (int i = 0; i < 8; i++) {
                int idx = tid + i * THREADS;
                cvt_store2(na[i], 1.0f, nH, nL, idx >> 4, idx & 15);
            }
            #pragma unroll
            for (int i = 0; i < 4; i++) {
                int idx = tid + i * THREADS;
                cvt_store2(nb[i], W_SCALE, mH, mL, idx >> 4, idx & 15);
            }
            // ---- 3. LDG(c+2) ----
            if (chunk + 2 < NCHUNK) load_chunk(A, W, m0, chunk + 2, tid, na, nb);
        }

        // ---- 4. fold segment (after mma results drain) ----
        #pragma unroll
        for (int mt = 0; mt < 2; mt++)
            #pragma unroll
            for (int nt = 0; nt < 4; nt++)
                #pragma unroll
                for (int j = 0; j < 4; j++)
                    accM[mt][nt][j] += fmaf(accS1[mt][nt][j], LO_FOLD, accS0[mt][nt][j]);

        __syncthreads();
    }

    // epilogue: undo W pre-scale (exact *2^-6)
    #pragma unroll
    for (int mt = 0; mt < 2; mt++) {
        const int r0  = m0 + rg * 32 + mt * 16 + (lane >> 2);
        const int col = eh * 32 + (lane & 3) * 2;
        #pragma unroll
        for (int nt = 0; nt < 4; nt++) {
            float* d0 = logits + (size_t)r0 * E_DIM + nt * 8 + col;
            float* d1 = logits + (size_t)(r0 + 8) * E_DIM + nt * 8 + col;
            *reinterpret_cast<float2*>(d0) =
                make_float2(accM[mt][nt][0] * OUT_SCALE, accM[mt][nt][1] * OUT_SCALE);
            *reinterpret_cast<float2*>(d1) =
                make_float2(accM[mt][nt][2] * OUT_SCALE, accM[mt][nt][3] * OUT_SCALE);
        }
    }
}

// ---------------------------------------------------------------------------
// Kernel 2: top-8 + renormalized softmax scores (unchanged, verified)
// ---------------------------------------------------------------------------
__global__ __launch_bounds__(256) void topk_kernel(
    const float* __restrict__ logits,
    float* __restrict__ scores,
    float* __restrict__ indices, int T)
{
    const int warp = (int)((blockIdx.x * blockDim.x + threadIdx.x) >> 5);
    const int lane = threadIdx.x & 31;
    if (warp >= T) return;

    const float* lg = logits + (size_t)warp * E_DIM;
    float v0 = lg[lane];
    float v1 = lg[lane + 32];

    float topv[TOPK];
    int   topi[TOPK];

    #pragma unroll
    for (int r = 0; r < TOPK; r++) {
        bool p   = (v0 >= v1);
        float lv = p ? v0 : v1;
        int   li = p ? lane : lane + 32;
        #pragma unroll
        for (int off = 16; off > 0; off >>= 1) {
            float ov = __shfl_xor_sync(0xffffffffu, lv, off);
            int   oi = __shfl_xor_sync(0xffffffffu, li, off);
            if (ov > lv || (ov == lv && oi < li)) { lv = ov; li = oi; }
        }
        topv[r] = lv; topi[r] = li;
        if (li == lane)           v0 = -INFINITY;
        else if (li == lane + 32) v1 = -INFINITY;
    }

    if (lane == 0) {
        const float m = topv[0];
        float e[TOPK], s = 0.f;
        #pragma unroll
        for (int r = 0; r < TOPK; r++) { e[r] = expf(topv[r] - m); s += e[r]; }
        const float inv = 1.f / s;
        #pragma unroll
        for (int r = 0; r < TOPK; r++) {
            scores [(size_t)warp * TOPK + r] = e[r] * inv;
            indices[(size_t)warp * TOPK + r] = (float)topi[r];
        }
    }
}

// ---------------------------------------------------------------------------
extern "C" void kernel_launch(void* const* d_in, const int* in_sizes, int n_in,
                              void* d_out, int out_size)
{
    const float* hs = (const float*)d_in[0];   // hidden_states [T, 4096]
    const float* w  = (const float*)d_in[1];   // weight        [64, 4096]
    const int T = in_sizes[0] / H_DIM;

    float* out     = (float*)d_out;
    float* logits  = out;
    float* scores  = out + (size_t)T * E_DIM;
    float* indices = scores + (size_t)T * TOPK;

    cudaFuncSetAttribute(router_gemm_tc, cudaFuncAttributeMaxDynamicSharedMemorySize, DYN_SZ);
    router_gemm_tc<<<T / BM, THREADS, DYN_SZ>>>(hs, w, logits);

    const int warps_per_block = 256 / 32;
    const int grid = (T + warps_per_block - 1) / warps_per_block;
    topk_kernel<<<grid, 256>>>(logits, scores, indices, T);
}

// round 17
// speedup vs baseline: 1.0153x; 1.0153x over previous
#include <cuda_runtime.h>
#include <cuda_fp16.h>
#include <math.h>
#include <stdint.h>

#define H_DIM 4096
#define E_DIM 64
#define TOPK  8
#define BM    128                 // tokens per CTA
#define KC    64                  // K per chunk (= one accumulation segment)
#define NCHUNK (H_DIM / KC)       // 64
#define THREADS 256               // 8 warps: 4 row-groups x 2 expert-halves

#define A_PL  (BM * KC * 2)       // 16384 B per A fp16 plane
#define B_PL  (E_DIM * KC * 2)    // 8192  B per B fp16 plane
#define STAGE_SZ (2 * A_PL + 2 * B_PL)   // 49152 B
#define NSTAGE 4
#define TILE_SZ (NSTAGE * STAGE_SZ)      // 196608 B
#define DYN_SZ (TILE_SZ + 256)

#define W_SCALE   64.0f           // W pre-scale (2^6, exact)
#define OUT_SCALE 0.015625f       // 2^-6
#define LO_SCALE  2048.0f         // lo-plane pre-scale (2^11, exact)
#define LO_FOLD   4.8828125e-4f   // 2^-11

__device__ __forceinline__ uint32_t s2u(const void* p) {
    uint32_t a;
    asm("{ .reg .u64 t; cvta.to.shared.u64 t, %1; cvt.u32.u64 %0, t; }" : "=r"(a) : "l"(p));
    return a;
}
__device__ __forceinline__ uint32_t swz(uint32_t b) { return b ^ ((b >> 3) & 0x70); }

// fp16 2-way split of one float4 (verified R11): v*scale = h + l*2^-11.
__device__ __forceinline__ void cvt_store2(float4 v, float scale,
                                           uint32_t hB, uint32_t lB, int row, int c4) {
    v.x *= scale; v.y *= scale; v.z *= scale; v.w *= scale;
    uint32_t h01, h23;
    asm("cvt.rn.f16x2.f32 %0, %1, %2;" : "=r"(h01) : "f"(v.y), "f"(v.x));
    asm("cvt.rn.f16x2.f32 %0, %1, %2;" : "=r"(h23) : "f"(v.w), "f"(v.z));
    float h0, h1, h2, h3;
    asm("{.reg .b16 lo,hi; mov.b32 {lo,hi}, %2; cvt.f32.f16 %0, lo; cvt.f32.f16 %1, hi;}"
        : "=f"(h0), "=f"(h1) : "r"(h01));
    asm("{.reg .b16 lo,hi; mov.b32 {lo,hi}, %2; cvt.f32.f16 %0, lo; cvt.f32.f16 %1, hi;}"
        : "=f"(h2), "=f"(h3) : "r"(h23));
    float r0 = (v.x - h0) * LO_SCALE, r1 = (v.y - h1) * LO_SCALE;
    float r2 = (v.z - h2) * LO_SCALE, r3 = (v.w - h3) * LO_SCALE;
    uint32_t l01, l23;
    asm("cvt.rn.f16x2.f32 %0, %1, %2;" : "=r"(l01) : "f"(r1), "f"(r0));
    asm("cvt.rn.f16x2.f32 %0, %1, %2;" : "=r"(l23) : "f"(r3), "f"(r2));
    uint32_t off = swz((uint32_t)(row * 128 + c4 * 8));
    asm volatile("st.shared.v2.b32 [%0], {%1,%2};" :: "r"(hB + off), "r"(h01), "r"(h23));
    asm volatile("st.shared.v2.b32 [%0], {%1,%2};" :: "r"(lB + off), "r"(l01), "r"(l23));
}

__device__ __forceinline__ void load_chunk(const float* __restrict__ A,
                                           const float* __restrict__ W,
                                           int m0, int chunk, int tid,
                                           float4* ra, float4* rb) {
    const int k0 = chunk * KC;
    #pragma unroll
    for (int i = 0; i < 8; i++) {                  // 8*256 = 2048 = 128 rows x 16
        int idx = tid + i * THREADS;
        int row = idx >> 4;
        int c4  = idx & 15;
        ra[i] = *reinterpret_cast<const float4*>(A + (size_t)(m0 + row) * H_DIM + k0 + c4 * 4);
    }
    #pragma unroll
    for (int i = 0; i < 4; i++) {                  // 4*256 = 1024 = 64 rows x 16
        int idx = tid + i * THREADS;
        int row = idx >> 4;
        int c4  = idx & 15;
        rb[i] = *reinterpret_cast<const float4*>(W + (size_t)row * H_DIM + k0 + c4 * 4);
    }
}

__device__ __forceinline__ void convert_chunk(const float4* ra, const float4* rb,
                                              uint32_t st, int tid) {
    const uint32_t aH = st, aL = st + A_PL;
    const uint32_t bH = aL + A_PL, bL = bH + B_PL;
    #pragma unroll
    for (int i = 0; i < 8; i++) {
        int idx = tid + i * THREADS;
        cvt_store2(ra[i], 1.0f, aH, aL, idx >> 4, idx & 15);
    }
    #pragma unroll
    for (int i = 0; i < 4; i++) {
        int idx = tid + i * THREADS;
        cvt_store2(rb[i], W_SCALE, bH, bL, idx >> 4, idx & 15);
    }
}

__device__ __forceinline__ void ldsm4(uint32_t addr, uint32_t& r0, uint32_t& r1,
                                      uint32_t& r2, uint32_t& r3) {
    asm volatile("ldmatrix.sync.aligned.m8n8.x4.shared.b16 {%0,%1,%2,%3}, [%4];"
                 : "=r"(r0), "=r"(r1), "=r"(r2), "=r"(r3) : "r"(addr));
}

__device__ __forceinline__ void mma16816(float* d, const uint32_t* a, const uint32_t* b) {
    asm volatile(
        "mma.sync.aligned.m16n8k16.row.col.f32.f16.f16.f32 "
        "{%0,%1,%2,%3}, {%4,%5,%6,%7}, {%8,%9}, {%0,%1,%2,%3};"
        : "+f"(d[0]), "+f"(d[1]), "+f"(d[2]), "+f"(d[3])
        : "r"(a[0]), "r"(a[1]), "r"(a[2]), "r"(a[3]), "r"(b[0]), "r"(b[1]));
}

// compute one chunk from stage st, fold into accM (numerics == R15)
__device__ __forceinline__ void compute_chunk(uint32_t st, uint32_t a_off0, uint32_t b_off0,
                                              float accM[2][4][4]) {
    const uint32_t aH = st, aL = st + A_PL;
    const uint32_t bH = aL + A_PL, bL = bH + B_PL;

    float accS0[2][4][4], accS1[2][4][4];
    #pragma unroll
    for (int mt = 0; mt < 2; mt++)
        #pragma unroll
        for (int nt = 0; nt < 4; nt++)
            #pragma unroll
            for (int j = 0; j < 4; j++) { accS0[mt][nt][j] = 0.f; accS1[mt][nt][j] = 0.f; }

    #pragma unroll
    for (int ks = 0; ks < 4; ks++) {
        const uint32_t ka = (uint32_t)(ks * 32);
        uint32_t ah[2][4], al[2][4];
        #pragma unroll
        for (int mt = 0; mt < 2; mt++) {
            const uint32_t ao = a_off0 + (uint32_t)(mt * 16 * 128) + ka;
            ldsm4(aH + swz(ao), ah[mt][0], ah[mt][1], ah[mt][2], ah[mt][3]);
            ldsm4(aL + swz(ao), al[mt][0], al[mt][1], al[mt][2], al[mt][3]);
        }

        uint32_t bh[4][2], bl[4][2];
        const uint32_t bo0 = swz(b_off0 + ka);
        const uint32_t bo1 = swz(b_off0 + 2048 + ka);
        ldsm4(bH + bo0, bh[0][0], bh[0][1], bh[1][0], bh[1][1]);
        ldsm4(bH + bo1, bh[2][0], bh[2][1], bh[3][0], bh[3][1]);
        ldsm4(bL + bo0, bl[0][0], bl[0][1], bl[1][0], bl[1][1]);
        ldsm4(bL + bo1, bl[2][0], bl[2][1], bl[3][0], bl[3][1]);

        #pragma unroll
        for (int mt = 0; mt < 2; mt++) {
            #pragma unroll
            for (int nt = 0; nt < 4; nt++) mma16816(accS0[mt][nt], ah[mt], bh[nt]);
            #pragma unroll
            for (int nt = 0; nt < 4; nt++) mma16816(accS1[mt][nt], al[mt], bh[nt]);
            #pragma unroll
            for (int nt = 0; nt < 4; nt++) mma16816(accS1[mt][nt], ah[mt], bl[nt]);
        }
    }

    #pragma unroll
    for (int mt = 0; mt < 2; mt++)
        #pragma unroll
        for (int nt = 0; nt < 4; nt++)
            #pragma unroll
            for (int j = 0; j < 4; j++)
                accM[mt][nt][j] += fmaf(accS1[mt][nt][j], LO_FOLD, accS0[mt][nt][j]);
}

// ---------------------------------------------------------------------------
// HMMA fp16 2-way-split GEMM (numerics == R15), 32x32 warp tiles,
// 4 smem stages -> ONE barrier per TWO chunks (stage reuse distance 4 > sync
// distance 2: convert(c) writes a stage last read at c-4, finished before the
// previous sync; compute(c) reads a stage written before the latest sync).
// ---------------------------------------------------------------------------
__global__ __launch_bounds__(THREADS, 1) void router_gemm_tc(
    const float* __restrict__ A, const float* __restrict__ W,
    float* __restrict__ logits)
{
    extern __shared__ char dsm[];
    const uint32_t base = (s2u(dsm) + 127u) & ~127u;

    const int tid  = threadIdx.x;
    const int warp = tid >> 5;
    const int lane = tid & 31;
    const int m0   = blockIdx.x * BM;

    const int rg = warp >> 1;     // row group 0..3: rows rg*32 .. rg*32+31
    const int eh = warp & 1;      // expert half: experts eh*32 .. eh*32+31

    const uint32_t a_off0 = (uint32_t)((rg * 32 + (lane & 15)) * 128 + (lane >> 4) * 16);
    const uint32_t b_off0 = (uint32_t)((((lane >> 4) << 3) + (lane & 7)) * 128 +
                                       ((lane >> 3) & 1) * 16 + eh * 2 * 2048);

    float accM[2][4][4];
    #pragma unroll
    for (int mt = 0; mt < 2; mt++)
        #pragma unroll
        for (int nt = 0; nt < 4; nt++)
            #pragma unroll
            for (int j = 0; j < 4; j++) accM[mt][nt][j] = 0.f;

    // ---- prologue: convert chunks 0,1; prefetch chunk 2 ----
    float4 na[8], nb[4];
    load_chunk(A, W, m0, 0, tid, na, nb);
    convert_chunk(na, nb, base + 0 * STAGE_SZ, tid);
    load_chunk(A, W, m0, 1, tid, na, nb);
    convert_chunk(na, nb, base + 1 * STAGE_SZ, tid);
    load_chunk(A, W, m0, 2, tid, na, nb);
    __syncthreads();

    for (int p = 0; p < NCHUNK / 2; ++p) {
        const int c0 = 2 * p;
        // convert(c0+2) from staged regs; refill regs with chunk c0+3
        if (c0 + 2 < NCHUNK) {
            convert_chunk(na, nb, base + (uint32_t)(((c0 + 2) & 3) * STAGE_SZ), tid);
            if (c0 + 3 < NCHUNK) load_chunk(A, W, m0, c0 + 3, tid, na, nb);
        }
        compute_chunk(base + (uint32_t)((c0 & 3) * STAGE_SZ), a_off0, b_off0, accM);

        // convert(c0+3); refill regs with chunk c0+4
        if (c0 + 3 < NCHUNK) {
            convert_chunk(na, nb, base + (uint32_t)(((c0 + 3) & 3) * STAGE_SZ), tid);
            if (c0 + 4 < NCHUNK) load_chunk(A, W, m0, c0 + 4, tid, na, nb);
        }
        compute_chunk(base + (uint32_t)(((c0 + 1) & 3) * STAGE_SZ), a_off0, b_off0, accM);

        __syncthreads();
    }

    // epilogue: undo W pre-scale (exact *2^-6)
    #pragma unroll
    for (int mt = 0; mt < 2; mt++) {
        const int r0  = m0 + rg * 32 + mt * 16 + (lane >> 2);
        const int col = eh * 32 + (lane & 3) * 2;
        #pragma unroll
        for (int nt = 0; nt < 4; nt++) {
            float* d0 = logits + (size_t)r0 * E_DIM + nt * 8 + col;
            float* d1 = logits + (size_t)(r0 + 8) * E_DIM + nt * 8 + col;
            *reinterpret_cast<float2*>(d0) =
                make_float2(accM[mt][nt][0] * OUT_SCALE, accM[mt][nt][1] * OUT_SCALE);
            *reinterpret_cast<float2*>(d1) =
                make_float2(accM[mt][nt][2] * OUT_SCALE, accM[mt][nt][3] * OUT_SCALE);
        }
    }
}

// ---------------------------------------------------------------------------
// Kernel 2: top-8 + renormalized softmax scores (unchanged, verified)
// ---------------------------------------------------------------------------
__global__ __launch_bounds__(256) void topk_kernel(
    const float* __restrict__ logits,
    float* __restrict__ scores,
    float* __restrict__ indices, int T)
{
    const int warp = (int)((blockIdx.x * blockDim.x + threadIdx.x) >> 5);
    const int lane = threadIdx.x & 31;
    if (warp >= T) return;

    const float* lg = logits + (size_t)warp * E_DIM;
    float v0 = lg[lane];
    float v1 = lg[lane + 32];

    float topv[TOPK];
    int   topi[TOPK];

    #pragma unroll
    for (int r = 0; r < TOPK; r++) {
        bool p   = (v0 >= v1);
        float lv = p ? v0 : v1;
        int   li = p ? lane : lane + 32;
        #pragma unroll
        for (int off = 16; off > 0; off >>= 1) {
            float ov = __shfl_xor_sync(0xffffffffu, lv, off);
            int   oi = __shfl_xor_sync(0xffffffffu, li, off);
            if (ov > lv || (ov == lv && oi < li)) { lv = ov; li = oi; }
        }
        topv[r] = lv; topi[r] = li;
        if (li == lane)           v0 = -INFINITY;
        else if (li == lane + 32) v1 = -INFINITY;
    }

    if (lane == 0) {
        const float m = topv[0];
        float e[TOPK], s = 0.f;
        #pragma unroll
        for (int r = 0; r < TOPK; r++) { e[r] = expf(topv[r] - m); s += e[r]; }
        const float inv = 1.f / s;
        #pragma unroll
        for (int r = 0; r < TOPK; r++) {
            scores [(size_t)warp * TOPK + r] = e[r] * inv;
            indices[(size_t)warp * TOPK + r] = (float)topi[r];
        }
    }
}

// ---------------------------------------------------------------------------
extern "C" void kernel_launch(void* const* d_in, const int* in_sizes, int n_in,
                              void* d_out, int out_size)
{
    const float* hs = (const float*)d_in[0];   // hidden_states [T, 4096]
    const float* w  = (const float*)d_in[1];   // weight        [64, 4096]
    const int T = in_sizes[0] / H_DIM;

    float* out     = (float*)d_out;
    float* logits  = out;
    float* scores  = out + (size_t)T * E_DIM;
    float* indices = scores + (size_t)T * TOPK;

    cudaFuncSetAttribute(router_gemm_tc, cudaFuncAttributeMaxDynamicSharedMemorySize, DYN_SZ);
    router_gemm_tc<<<T / BM, THREADS, DYN_SZ>>>(hs, w, logits);

    const int warps_per_block = 256 / 32;
    const int grid = (T + warps_per_block - 1) / warps_per_block;
    topk_kernel<<<grid, 256>>>(logits, scores, indices, T);
}